// round 5
// baseline (speedup 1.0000x reference)
#include <cuda_runtime.h>
#include <cuda_bf16.h>
#include <cstddef>

// ---------------------------------------------------------------------------
// DCT_61340722921773
//
// Reference semantics: x = inputs.reshape(b, -1, 64); out[p,f] = sum_s x[p,s]*K[s,f]
// with K[u*8+v, i*8+j] = C[u,i]*C[v,j],  C[u,i] = s(u)*cos((2i+1)*u*pi/16).
// Per contiguous 64-float vector (viewed as 8x8 X[u][v]):  Y = C^T * X * C.
//
// Strategy: one thread per 64-float patch, separable transform with the DCT
// basis baked in as compile-time float literals -> FFMA-with-immediate
// (rt_SMSP=1, 2x the 3-reg FFMA rate). 1024 FMA/patch instead of 4096.
// Streaming 201 MB total -> memory-bound, target ~32 us.
// ---------------------------------------------------------------------------

#define CA 0.35355339059327373f   // sqrt(1/8)
#define C1 0.4903926402016152f    // 0.5*cos( 1*pi/16)
#define C2 0.46193976625564337f   // 0.5*cos( 2*pi/16)
#define C3 0.4157348061512726f    // 0.5*cos( 3*pi/16)
#define C4 0.35355339059327373f   // 0.5*cos( 4*pi/16)
#define C5 0.2777851165098011f    // 0.5*cos( 5*pi/16)
#define C6 0.1913417161825449f    // 0.5*cos( 6*pi/16)
#define C7 0.09754516100806412f   // 0.5*cos( 7*pi/16)

// Cmat[u][i] = s(u) * cos((2i+1)*u*pi/16)
__device__ constexpr float Cmat[8][8] = {
    {  CA,  CA,  CA,  CA,  CA,  CA,  CA,  CA },
    {  C1,  C3,  C5,  C7, -C7, -C5, -C3, -C1 },
    {  C2,  C6, -C6, -C2, -C2, -C6,  C6,  C2 },
    {  C3, -C7, -C1, -C5,  C5,  C1,  C7, -C3 },
    {  C4, -C4, -C4,  C4,  C4, -C4, -C4,  C4 },
    {  C5, -C1,  C7,  C3, -C3, -C7,  C1, -C5 },
    {  C6, -C2,  C2, -C6, -C6,  C2, -C2,  C6 },
    {  C7, -C5,  C3, -C1,  C1, -C3,  C5, -C7 },
};

__global__ void __launch_bounds__(128)
dct_sep_kernel(const float4* __restrict__ in, float4* __restrict__ out, int npatch)
{
    int p = blockIdx.x * 128 + threadIdx.x;
    if (p >= npatch) return;

    const float4* src = in + (size_t)p * 16;

    // Load the full 64-float patch up front: 16 independent LDG.128 (MLP=16).
    float4 v[16];
#pragma unroll
    for (int r = 0; r < 16; ++r) v[r] = src[r];

    float X[64];
#pragma unroll
    for (int r = 0; r < 16; ++r) {
        X[4 * r + 0] = v[r].x;
        X[4 * r + 1] = v[r].y;
        X[4 * r + 2] = v[r].z;
        X[4 * r + 3] = v[r].w;
    }

    // Stage 1: T[u][j] = sum_v X[u][v] * C[v][j]   (column transform)
    float T[64];
#pragma unroll
    for (int u = 0; u < 8; ++u) {
#pragma unroll
        for (int j = 0; j < 8; ++j) {
            float acc = X[u * 8 + 0] * Cmat[0][j];
#pragma unroll
            for (int vv = 1; vv < 8; ++vv)
                acc = fmaf(X[u * 8 + vv], Cmat[vv][j], acc);
            T[u * 8 + j] = acc;
        }
    }

    // Stage 2: Y[i][j] = sum_u C[u][i] * T[u][j]   (row transform), store rows.
    float4* dst = out + (size_t)p * 16;
#pragma unroll
    for (int i = 0; i < 8; ++i) {
        float y[8];
#pragma unroll
        for (int j = 0; j < 8; ++j) {
            float acc = T[0 * 8 + j] * Cmat[0][i];
#pragma unroll
            for (int u = 1; u < 8; ++u)
                acc = fmaf(Cmat[u][i], T[u * 8 + j], acc);
            y[j] = acc;
        }
        dst[2 * i + 0] = make_float4(y[0], y[1], y[2], y[3]);
        dst[2 * i + 1] = make_float4(y[4], y[5], y[6], y[7]);
    }
}

extern "C" void kernel_launch(void* const* d_in, const int* in_sizes, int n_in,
                              void* d_out, int out_size)
{
    // d_in[0]: inputs, float32, (8,3,1024,1024) = 25165824 elements
    // d_in[1]: kernel, float32, (64,64) — unused: the DCT basis is baked in
    //          as compile-time constants (identical formula to the reference).
    const float4* in  = (const float4*)d_in[0];
    float4*       out = (float4*)d_out;

    int n      = in_sizes[0];
    int npatch = n / 64;          // 393216

    int threads = 128;
    int blocks  = (npatch + threads - 1) / threads;
    dct_sep_kernel<<<blocks, threads>>>(in, out, npatch);
}

// round 8
// speedup vs baseline: 1.7300x; 1.7300x over previous
#include <cuda_runtime.h>
#include <cuda_bf16.h>
#include <cstddef>

// ---------------------------------------------------------------------------
// DCT_61340722921773 — round 5
//
// out[p,f] = sum_s x[p,s] * K[s,f],  K = kron(C, C)  ==>  per 8x8 patch:
// Y = C^T * X * C  (separable, DCT basis baked in as immediates).
//
// Round-4 lesson (ncu): one-thread-per-patch makes every warp LDG/STG touch
// 32 lines -> 32 L1 wavefronts/patch -> L1-bound at 71.7% with DRAM at 35%.
//
// This round: 8 threads per patch.
//  * stage 1: thread (p,u) loads row u (2x LDG.128, warp = 1KB contiguous,
//    4 wf/patch), computes T[u][:] locally (64 imm-FFMA).
//  * T scattered to smem column-major (col stride 12, patch stride 104):
//    STS.32 and stage-2 LDS.128 both provably bank-conflict-free.
//  * stage 2: thread (p,j) reads column T[:,j] (2x LDS.128), computes
//    Y[:,j] locally, scatters rows to a second smem region (stride 72,
//    conflict-free), which is then read linearly and stored fully coalesced.
// L1 phases ~14/patch (~19us) and FMA ~11us, both < ~31us DRAM floor.
// ---------------------------------------------------------------------------

#define CA 0.35355339059327373f   // sqrt(1/8)
#define C1 0.4903926402016152f
#define C2 0.46193976625564337f
#define C3 0.4157348061512726f
#define C4 0.35355339059327373f
#define C5 0.2777851165098011f
#define C6 0.1913417161825449f
#define C7 0.09754516100806412f

// Cmat[u][i] = s(u) * cos((2i+1)*u*pi/16)
__device__ constexpr float Cmat[8][8] = {
    {  CA,  CA,  CA,  CA,  CA,  CA,  CA,  CA },
    {  C1,  C3,  C5,  C7, -C7, -C5, -C3, -C1 },
    {  C2,  C6, -C6, -C2, -C2, -C6,  C6,  C2 },
    {  C3, -C7, -C1, -C5,  C5,  C1,  C7, -C3 },
    {  C4, -C4, -C4,  C4,  C4, -C4, -C4,  C4 },
    {  C5, -C1,  C7,  C3, -C3, -C7,  C1, -C5 },
    {  C6, -C2,  C2, -C6, -C6,  C2, -C2,  C6 },
    {  C7, -C5,  C3, -C1,  C1, -C3,  C5, -C7 },
};

constexpr int PPB      = 32;    // patches per block
constexpr int THREADS  = 256;   // 8 threads per patch
constexpr int T_STRIDE = 104;   // T region: [p][j][u], col stride 12, +8 pad
constexpr int Y_STRIDE = 72;    // Y region: [p][i][j], row stride 8, +8 pad

__global__ void __launch_bounds__(THREADS)
dct8_kernel(const float4* __restrict__ in, float4* __restrict__ out, int npatch)
{
    __shared__ float sT[PPB * T_STRIDE];   // 13312 B
    __shared__ float sY[PPB * Y_STRIDE];   //  9216 B

    const int t  = threadIdx.x;
    const int pl = t >> 3;                 // local patch 0..31
    const int u  = t & 7;                  // row (stage 1) / column j (stage 2)
    const int pg = blockIdx.x * PPB + pl;  // global patch

    // ---- Stage 1: row transform  T[u][j] = sum_v X[u][v] * C[v][j] ----
    if (pg < npatch) {
        const float4* src = in + (size_t)pg * 16 + u * 2;
        float4 a = src[0];
        float4 b = src[1];
        float x[8] = { a.x, a.y, a.z, a.w, b.x, b.y, b.z, b.w };

        float* tp = sT + pl * T_STRIDE + u;      // column-major: + 12*j
#pragma unroll
        for (int j = 0; j < 8; ++j) {
            float acc = x[0] * Cmat[0][j];
#pragma unroll
            for (int v = 1; v < 8; ++v)
                acc = fmaf(x[v], Cmat[v][j], acc);
            tp[12 * j] = acc;                    // STS.32, conflict-free
        }
    }
    __syncthreads();

    // ---- Stage 2: column transform  Y[i][j] = sum_u C[u][i] * T[u][j] ----
    if (pg < npatch) {
        const float4* tc =
            (const float4*)(sT + pl * T_STRIDE + 12 * u);  // 16B-aligned
        float4 c0 = tc[0];                       // LDS.128, conflict-free
        float4 c1 = tc[1];
        float Tc[8] = { c0.x, c0.y, c0.z, c0.w, c1.x, c1.y, c1.z, c1.w };

        float* yp = sY + pl * Y_STRIDE + u;      // row-major: + 8*i
#pragma unroll
        for (int i = 0; i < 8; ++i) {
            float acc = Tc[0] * Cmat[0][i];
#pragma unroll
            for (int uu = 1; uu < 8; ++uu)
                acc = fmaf(Cmat[uu][i], Tc[uu], acc);
            yp[8 * i] = acc;                     // STS.32, conflict-free
        }
    }
    __syncthreads();

    // ---- Coalesced output: 512 float4 per block, linear ----
    const size_t base_f4 = (size_t)blockIdx.x * PPB * 16;
#pragma unroll
    for (int k = 0; k < 2; ++k) {
        int fl  = t + k * THREADS;               // 0..511
        int p2  = fl >> 4;
        int rem = fl & 15;
        if (blockIdx.x * PPB + p2 < npatch) {
            const float4* s =
                (const float4*)(sY + p2 * Y_STRIDE + rem * 4);  // conflict-free
            out[base_f4 + fl] = *s;              // STG.128, fully coalesced
        }
    }
}

extern "C" void kernel_launch(void* const* d_in, const int* in_sizes, int n_in,
                              void* d_out, int out_size)
{
    // d_in[0]: inputs, float32, (8,3,1024,1024); d_in[1]: 64x64 DCT matrix
    // (unused — basis baked in as immediates, identical formula).
    const float4* in  = (const float4*)d_in[0];
    float4*       out = (float4*)d_out;

    int npatch = in_sizes[0] / 64;               // 393216
    int blocks = (npatch + PPB - 1) / PPB;       // 12288

    dct8_kernel<<<blocks, THREADS>>>(in, out, npatch);
}